// round 1
// baseline (speedup 1.0000x reference)
#include <cuda_runtime.h>
#include <cuda_bf16.h>
#include <cstdint>
#include <cstddef>

// GPT-2 small config
#define LNUM 12
#define EDIM 768
#define HNUM 12
#define HDIM 64
#define TSEQ 1024
#define BATCH 2
#define MROWS (BATCH * TSEQ)   // 2048
#define VOCAB 50257

// ---------------- scratch (device globals; no allocations allowed) -------------
__device__ __align__(256) float g_x[MROWS * EDIM];
__device__ __align__(256) float g_ln[MROWS * EDIM];
__device__ __align__(256) float g_qkv[MROWS * 3 * EDIM];
__device__ __align__(256) float g_attn[MROWS * EDIM];
__device__ __align__(256) float g_fc[MROWS * 4 * EDIM];

// ---------------- helpers ------------------------------------------------------
__device__ __forceinline__ float warp_sum(float v) {
#pragma unroll
    for (int o = 16; o; o >>= 1) v += __shfl_xor_sync(0xffffffffu, v, o);
    return v;
}
__device__ __forceinline__ float warp_max(float v) {
#pragma unroll
    for (int o = 16; o; o >>= 1) v = fmaxf(v, __shfl_xor_sync(0xffffffffu, v, o));
    return v;
}

// block reduce sum (nwarps <= 8). red must have >= nwarps floats.
__device__ __forceinline__ float block_sum(float v, float* red, int nwarps) {
    int lane = threadIdx.x & 31, w = threadIdx.x >> 5;
    v = warp_sum(v);
    if (lane == 0) red[w] = v;
    __syncthreads();
    if (threadIdx.x == 0) {
        float s = 0.f;
        for (int i = 0; i < nwarps; i++) s += red[i];
        red[0] = s;
    }
    __syncthreads();
    float r = red[0];
    __syncthreads();
    return r;
}
__device__ __forceinline__ float block_max(float v, float* red, int nwarps) {
    int lane = threadIdx.x & 31, w = threadIdx.x >> 5;
    v = warp_max(v);
    if (lane == 0) red[w] = v;
    __syncthreads();
    if (threadIdx.x == 0) {
        float s = -1e30f;
        for (int i = 0; i < nwarps; i++) s = fmaxf(s, red[i]);
        red[0] = s;
    }
    __syncthreads();
    float r = red[0];
    __syncthreads();
    return r;
}

// ---------------- embedding ----------------------------------------------------
__global__ void embed_kernel(const int* __restrict__ idx,
                             const float* __restrict__ wte,
                             const float* __restrict__ wpe,
                             float* __restrict__ x) {
    int r = blockIdx.x;            // 0..2047
    int t = r & (TSEQ - 1);        // position
    int token = idx[r];
    const float* wt = wte + (size_t)token * EDIM;
    const float* wp = wpe + (size_t)t * EDIM;
    float* xr = x + (size_t)r * EDIM;
    for (int e = threadIdx.x; e < EDIM; e += blockDim.x)
        xr[e] = wt[e] + wp[e];
}

// ---------------- layernorm (rows of 768) -------------------------------------
__global__ __launch_bounds__(256) void ln_kernel(const float* __restrict__ in,
                                                 const float* __restrict__ w,
                                                 const float* __restrict__ b,
                                                 float* __restrict__ out) {
    __shared__ float red[8];
    int r = blockIdx.x;
    const float* x = in + (size_t)r * EDIM;
    float vals[3];
    float s = 0.f, s2 = 0.f;
#pragma unroll
    for (int i = 0; i < 3; i++) {
        float v = x[threadIdx.x + i * 256];
        vals[i] = v;
        s += v;
        s2 += v * v;
    }
    s = block_sum(s, red, 8);
    s2 = block_sum(s2, red, 8);
    float mu = s * (1.0f / EDIM);
    float var = s2 * (1.0f / EDIM) - mu * mu;
    float rstd = rsqrtf(var + 1e-5f);
    float* o = out + (size_t)r * EDIM;
#pragma unroll
    for (int i = 0; i < 3; i++) {
        int e = threadIdx.x + i * 256;
        o[e] = (vals[i] - mu) * rstd * w[e] + b[e];
    }
}

// ---------------- sgemm (NN): C[M,N] = A[M,K] @ B[K,N] + bias (+res) (gelu?) ---
// Requires M%128==0, N%128==0, K%16==0. 128x128 tile, 8x8 per thread (split 64+64).
__global__ __launch_bounds__(256) void sgemm_nn(int M, int N, int K,
                                                const float* __restrict__ A,
                                                const float* __restrict__ B,
                                                const float* __restrict__ bias,
                                                const float* __restrict__ res,
                                                float* __restrict__ C,
                                                int do_gelu) {
    __shared__ float As[16][132];
    __shared__ float Bs[16][128];
    int t = threadIdx.x;
    int m0 = blockIdx.y * 128;
    int n0 = blockIdx.x * 128;
    int tx = t & 15, ty = t >> 4;

    float acc[8][8];
#pragma unroll
    for (int i = 0; i < 8; i++)
#pragma unroll
        for (int j = 0; j < 8; j++) acc[i][j] = 0.f;

    for (int k0 = 0; k0 < K; k0 += 16) {
        // A tile: 128 rows x 16 cols -> As[k][m]
#pragma unroll
        for (int i = 0; i < 2; i++) {
            int f = t + i * 256;
            int row = f >> 2, c4 = (f & 3) * 4;
            float4 v = *reinterpret_cast<const float4*>(&A[(size_t)(m0 + row) * K + k0 + c4]);
            As[c4 + 0][row] = v.x;
            As[c4 + 1][row] = v.y;
            As[c4 + 2][row] = v.z;
            As[c4 + 3][row] = v.w;
        }
        // B tile: 16 rows x 128 cols -> Bs[k][n]
#pragma unroll
        for (int i = 0; i < 2; i++) {
            int f = t + i * 256;
            int kk = f >> 5, c4 = (f & 31) * 4;
            float4 v = *reinterpret_cast<const float4*>(&B[(size_t)(k0 + kk) * N + n0 + c4]);
            *reinterpret_cast<float4*>(&Bs[kk][c4]) = v;
        }
        __syncthreads();
#pragma unroll
        for (int kk = 0; kk < 16; kk++) {
            float4 a0 = *reinterpret_cast<const float4*>(&As[kk][ty * 4]);
            float4 a1 = *reinterpret_cast<const float4*>(&As[kk][64 + ty * 4]);
            float4 b0 = *reinterpret_cast<const float4*>(&Bs[kk][tx * 4]);
            float4 b1 = *reinterpret_cast<const float4*>(&Bs[kk][64 + tx * 4]);
            float a[8] = {a0.x, a0.y, a0.z, a0.w, a1.x, a1.y, a1.z, a1.w};
            float b[8] = {b0.x, b0.y, b0.z, b0.w, b1.x, b1.y, b1.z, b1.w};
#pragma unroll
            for (int i = 0; i < 8; i++)
#pragma unroll
                for (int j = 0; j < 8; j++) acc[i][j] = fmaf(a[i], b[j], acc[i][j]);
        }
        __syncthreads();
    }

#pragma unroll
    for (int ii = 0; ii < 2; ii++)
#pragma unroll
        for (int i = 0; i < 4; i++) {
            int m = m0 + ii * 64 + ty * 4 + i;
#pragma unroll
            for (int jj = 0; jj < 2; jj++)
#pragma unroll
                for (int j = 0; j < 4; j++) {
                    int n = n0 + jj * 64 + tx * 4 + j;
                    float v = acc[ii * 4 + i][jj * 4 + j];
                    if (bias) v += bias[n];
                    if (res) v += res[(size_t)m * N + n];
                    if (do_gelu) {
                        float xx = v;
                        v = 0.5f * xx * (1.0f + tanhf(0.7978845608028654f * (xx + 0.044715f * xx * xx * xx)));
                    }
                    C[(size_t)m * N + n] = v;
                }
        }
}

// ---------------- sgemm (NT): C[M,N] = A[M,K] @ B^T, B is [N,K] row-major ------
// For tied lm_head: N=50257 (edge-guarded). M%128==0, K%16==0.
__global__ __launch_bounds__(256) void sgemm_nt(int M, int N, int K,
                                                const float* __restrict__ A,
                                                const float* __restrict__ B,
                                                float* __restrict__ C) {
    __shared__ float As[16][132];
    __shared__ float Bs[16][132];
    int t = threadIdx.x;
    int m0 = blockIdx.y * 128;
    int n0 = blockIdx.x * 128;
    int tx = t & 15, ty = t >> 4;

    float acc[8][8];
#pragma unroll
    for (int i = 0; i < 8; i++)
#pragma unroll
        for (int j = 0; j < 8; j++) acc[i][j] = 0.f;

    for (int k0 = 0; k0 < K; k0 += 16) {
#pragma unroll
        for (int i = 0; i < 2; i++) {
            int f = t + i * 256;
            int row = f >> 2, c4 = (f & 3) * 4;
            float4 v = *reinterpret_cast<const float4*>(&A[(size_t)(m0 + row) * K + k0 + c4]);
            As[c4 + 0][row] = v.x;
            As[c4 + 1][row] = v.y;
            As[c4 + 2][row] = v.z;
            As[c4 + 3][row] = v.w;
        }
        // B tile from [N,K]: rows are n, cols are k
#pragma unroll
        for (int i = 0; i < 2; i++) {
            int f = t + i * 256;
            int n = f >> 2, c4 = (f & 3) * 4;
            float4 v = make_float4(0.f, 0.f, 0.f, 0.f);
            if (n0 + n < N)
                v = *reinterpret_cast<const float4*>(&B[(size_t)(n0 + n) * K + k0 + c4]);
            Bs[c4 + 0][n] = v.x;
            Bs[c4 + 1][n] = v.y;
            Bs[c4 + 2][n] = v.z;
            Bs[c4 + 3][n] = v.w;
        }
        __syncthreads();
#pragma unroll
        for (int kk = 0; kk < 16; kk++) {
            float4 a0 = *reinterpret_cast<const float4*>(&As[kk][ty * 4]);
            float4 a1 = *reinterpret_cast<const float4*>(&As[kk][64 + ty * 4]);
            float4 b0 = *reinterpret_cast<const float4*>(&Bs[kk][tx * 4]);
            float4 b1 = *reinterpret_cast<const float4*>(&Bs[kk][64 + tx * 4]);
            float a[8] = {a0.x, a0.y, a0.z, a0.w, a1.x, a1.y, a1.z, a1.w};
            float b[8] = {b0.x, b0.y, b0.z, b0.w, b1.x, b1.y, b1.z, b1.w};
#pragma unroll
            for (int i = 0; i < 8; i++)
#pragma unroll
                for (int j = 0; j < 8; j++) acc[i][j] = fmaf(a[i], b[j], acc[i][j]);
        }
        __syncthreads();
    }

#pragma unroll
    for (int ii = 0; ii < 2; ii++)
#pragma unroll
        for (int i = 0; i < 4; i++) {
            int m = m0 + ii * 64 + ty * 4 + i;
#pragma unroll
            for (int jj = 0; jj < 2; jj++)
#pragma unroll
                for (int j = 0; j < 4; j++) {
                    int n = n0 + jj * 64 + tx * 4 + j;
                    if (n < N) C[(size_t)m * N + n] = acc[ii * 4 + i][jj * 4 + j];
                }
        }
}

// ---------------- fused causal attention (per query row) -----------------------
// grid: (T, H, B), block: 128. qkv rows: [q(0..767) | k(768..1535) | v(1536..2303)]
__global__ __launch_bounds__(128) void attn_kernel(const float* __restrict__ qkv,
                                                   float* __restrict__ out) {
    __shared__ float sq[HDIM];
    __shared__ float ss[TSEQ];
    __shared__ float red[4];
    int tq = blockIdx.x;
    int h = blockIdx.y;
    int b = blockIdx.z;
    int tid = threadIdx.x;

    const int row = b * TSEQ + tq;
    const float* qptr = qkv + (size_t)row * (3 * EDIM) + h * HDIM;
    if (tid < HDIM) sq[tid] = qptr[tid];
    __syncthreads();

    const int nk = tq + 1;
    const float* kbase = qkv + (size_t)b * TSEQ * (3 * EDIM) + EDIM + h * HDIM;
    const float* vbase = qkv + (size_t)b * TSEQ * (3 * EDIM) + 2 * EDIM + h * HDIM;
    const float4* sq4 = reinterpret_cast<const float4*>(sq);

    float lmax = -1e30f;
    for (int k = tid; k < nk; k += 128) {
        const float4* kp4 = reinterpret_cast<const float4*>(kbase + (size_t)k * (3 * EDIM));
        float dot = 0.f;
#pragma unroll
        for (int d = 0; d < 16; d++) {
            float4 kv = kp4[d];
            float4 qv = sq4[d];
            dot = fmaf(qv.x, kv.x, dot);
            dot = fmaf(qv.y, kv.y, dot);
            dot = fmaf(qv.z, kv.z, dot);
            dot = fmaf(qv.w, kv.w, dot);
        }
        dot *= 0.125f;  // 1/sqrt(64)
        ss[k] = dot;
        lmax = fmaxf(lmax, dot);
    }
    float gmax = block_max(lmax, red, 4);

    float lsum = 0.f;
    for (int k = tid; k < nk; k += 128) {
        float e = __expf(ss[k] - gmax);
        ss[k] = e;
        lsum += e;
    }
    float gsum = block_sum(lsum, red, 4);
    float inv = 1.0f / gsum;
    __syncthreads();

    if (tid < HDIM) {
        float a0 = 0.f, a1 = 0.f, a2 = 0.f, a3 = 0.f;
        int k = 0;
        for (; k + 4 <= nk; k += 4) {
            a0 = fmaf(ss[k + 0], vbase[(size_t)(k + 0) * (3 * EDIM) + tid], a0);
            a1 = fmaf(ss[k + 1], vbase[(size_t)(k + 1) * (3 * EDIM) + tid], a1);
            a2 = fmaf(ss[k + 2], vbase[(size_t)(k + 2) * (3 * EDIM) + tid], a2);
            a3 = fmaf(ss[k + 3], vbase[(size_t)(k + 3) * (3 * EDIM) + tid], a3);
        }
        for (; k < nk; k++)
            a0 = fmaf(ss[k], vbase[(size_t)k * (3 * EDIM) + tid], a0);
        out[(size_t)row * EDIM + h * HDIM + tid] = (a0 + a1 + a2 + a3) * inv;
    }
}

// ---------------- launch -------------------------------------------------------
extern "C" void kernel_launch(void* const* d_in, const int* in_sizes, int n_in,
                              void* d_out, int out_size) {
    const int* idx = (const int*)d_in[0];
    const float* wte = (const float*)d_in[1];
    const float* wpe = (const float*)d_in[2];
    const float* ln1_w = (const float*)d_in[3];
    const float* ln1_b = (const float*)d_in[4];
    const float* attn_w = (const float*)d_in[5];
    const float* attn_b = (const float*)d_in[6];
    const float* attn_proj_w = (const float*)d_in[7];
    const float* attn_proj_b = (const float*)d_in[8];
    const float* ln2_w = (const float*)d_in[9];
    const float* ln2_b = (const float*)d_in[10];
    const float* fc_w = (const float*)d_in[11];
    const float* fc_b = (const float*)d_in[12];
    const float* fc_proj_w = (const float*)d_in[13];
    const float* fc_proj_b = (const float*)d_in[14];
    const float* lnf_w = (const float*)d_in[15];
    const float* lnf_b = (const float*)d_in[16];
    float* out = (float*)d_out;

    float *x, *ln, *qkv, *attn, *fc;
    cudaGetSymbolAddress((void**)&x, g_x);
    cudaGetSymbolAddress((void**)&ln, g_ln);
    cudaGetSymbolAddress((void**)&qkv, g_qkv);
    cudaGetSymbolAddress((void**)&attn, g_attn);
    cudaGetSymbolAddress((void**)&fc, g_fc);

    embed_kernel<<<MROWS, 256>>>(idx, wte, wpe, x);

    for (int l = 0; l < LNUM; l++) {
        ln_kernel<<<MROWS, 256>>>(x, ln1_w + l * EDIM, ln1_b + l * EDIM, ln);
        sgemm_nn<<<dim3(3 * EDIM / 128, MROWS / 128), 256>>>(
            MROWS, 3 * EDIM, EDIM, ln, attn_w + (size_t)l * EDIM * 3 * EDIM,
            attn_b + (size_t)l * 3 * EDIM, nullptr, qkv, 0);
        attn_kernel<<<dim3(TSEQ, HNUM, BATCH), 128>>>(qkv, attn);
        sgemm_nn<<<dim3(EDIM / 128, MROWS / 128), 256>>>(
            MROWS, EDIM, EDIM, attn, attn_proj_w + (size_t)l * EDIM * EDIM,
            attn_proj_b + (size_t)l * EDIM, x, x, 0);
        ln_kernel<<<MROWS, 256>>>(x, ln2_w + l * EDIM, ln2_b + l * EDIM, ln);
        sgemm_nn<<<dim3(4 * EDIM / 128, MROWS / 128), 256>>>(
            MROWS, 4 * EDIM, EDIM, ln, fc_w + (size_t)l * EDIM * 4 * EDIM,
            fc_b + (size_t)l * 4 * EDIM, nullptr, fc, 1);
        sgemm_nn<<<dim3(EDIM / 128, MROWS / 128), 256>>>(
            MROWS, EDIM, 4 * EDIM, fc, fc_proj_w + (size_t)l * 4 * EDIM * EDIM,
            fc_proj_b + (size_t)l * EDIM, x, x, 0);
    }

    ln_kernel<<<MROWS, 256>>>(x, lnf_w, lnf_b, ln);
    sgemm_nt<<<dim3((VOCAB + 127) / 128, MROWS / 128), 256>>>(
        MROWS, VOCAB, EDIM, ln, wte, out);
}

// round 3
// speedup vs baseline: 1.7258x; 1.7258x over previous
#include <cuda_runtime.h>
#include <cuda_bf16.h>
#include <cstdint>
#include <cstddef>

// GPT-2 small config
#define LNUM 12
#define EDIM 768
#define HNUM 12
#define HDIM 64
#define TSEQ 1024
#define BATCH 2
#define MROWS (BATCH * TSEQ)   // 2048
#define VOCAB 50257

// ---------------- scratch (device globals; no allocations allowed) -------------
__device__ __align__(256) float g_x[MROWS * EDIM];
__device__ __align__(256) float g_ln[MROWS * EDIM];
__device__ __align__(256) float g_qkv[MROWS * 3 * EDIM];
__device__ __align__(256) float g_attn[MROWS * EDIM];
__device__ __align__(256) float g_fc[MROWS * 4 * EDIM];

// ---------------- helpers ------------------------------------------------------
__device__ __forceinline__ float warp_sum(float v) {
#pragma unroll
    for (int o = 16; o; o >>= 1) v += __shfl_xor_sync(0xffffffffu, v, o);
    return v;
}
__device__ __forceinline__ float warp_max(float v) {
#pragma unroll
    for (int o = 16; o; o >>= 1) v = fmaxf(v, __shfl_xor_sync(0xffffffffu, v, o));
    return v;
}
__device__ __forceinline__ float block_sum(float v, float* red, int nwarps) {
    int lane = threadIdx.x & 31, w = threadIdx.x >> 5;
    v = warp_sum(v);
    if (lane == 0) red[w] = v;
    __syncthreads();
    if (threadIdx.x == 0) {
        float s = 0.f;
        for (int i = 0; i < nwarps; i++) s += red[i];
        red[0] = s;
    }
    __syncthreads();
    float r = red[0];
    __syncthreads();
    return r;
}
__device__ __forceinline__ float block_max(float v, float* red, int nwarps) {
    int lane = threadIdx.x & 31, w = threadIdx.x >> 5;
    v = warp_max(v);
    if (lane == 0) red[w] = v;
    __syncthreads();
    if (threadIdx.x == 0) {
        float s = -1e30f;
        for (int i = 0; i < nwarps; i++) s = fmaxf(s, red[i]);
        red[0] = s;
    }
    __syncthreads();
    float r = red[0];
    __syncthreads();
    return r;
}

__device__ __forceinline__ float tf32r(float x) {
    uint32_t u;
    asm("cvt.rna.tf32.f32 %0, %1;" : "=r"(u) : "f"(x));
    return __uint_as_float(u);
}
__device__ __forceinline__ void mma_tf32(float* d, const uint32_t* a, const uint32_t* b) {
    asm volatile(
        "mma.sync.aligned.m16n8k8.row.col.f32.tf32.tf32.f32 "
        "{%0,%1,%2,%3},{%4,%5,%6,%7},{%8,%9},{%0,%1,%2,%3};"
        : "+f"(d[0]), "+f"(d[1]), "+f"(d[2]), "+f"(d[3])
        : "r"(a[0]), "r"(a[1]), "r"(a[2]), "r"(a[3]), "r"(b[0]), "r"(b[1]));
}
__device__ __forceinline__ float gelu_f(float x) {
    return 0.5f * x * (1.0f + tanhf(0.7978845608028654f * (x + 0.044715f * x * x * x)));
}

// ---------------- embedding ----------------------------------------------------
__global__ void embed_kernel(const int* __restrict__ idx,
                             const float* __restrict__ wte,
                             const float* __restrict__ wpe,
                             float* __restrict__ x) {
    int r = blockIdx.x;
    int t = r & (TSEQ - 1);
    int token = idx[r];
    const float* wt = wte + (size_t)token * EDIM;
    const float* wp = wpe + (size_t)t * EDIM;
    float* xr = x + (size_t)r * EDIM;
    for (int e = threadIdx.x; e < EDIM; e += blockDim.x)
        xr[e] = wt[e] + wp[e];
}

// ---------------- layernorm ----------------------------------------------------
__global__ __launch_bounds__(256) void ln_kernel(const float* __restrict__ in,
                                                 const float* __restrict__ w,
                                                 const float* __restrict__ b,
                                                 float* __restrict__ out) {
    __shared__ float red[8];
    int r = blockIdx.x;
    const float* x = in + (size_t)r * EDIM;
    float vals[3];
    float s = 0.f, s2 = 0.f;
#pragma unroll
    for (int i = 0; i < 3; i++) {
        float v = x[threadIdx.x + i * 256];
        vals[i] = v;
        s += v;
        s2 += v * v;
    }
    s = block_sum(s, red, 8);
    s2 = block_sum(s2, red, 8);
    float mu = s * (1.0f / EDIM);
    float var = s2 * (1.0f / EDIM) - mu * mu;
    float rstd = rsqrtf(var + 1e-5f);
    float* o = out + (size_t)r * EDIM;
#pragma unroll
    for (int i = 0; i < 3; i++) {
        int e = threadIdx.x + i * 256;
        o[e] = (vals[i] - mu) * rstd * w[e] + b[e];
    }
}

// ================= tf32 tensor-core GEMM (NN) ==================================
// C[M,N] = A[M,K] @ B[K,N] (+bias)(+res)(gelu?). M%128==0, N%128==0, K%32==0.
// Block 128x128, BK=32, 256 threads = 8 warps at 64x32 warp tiles.
__global__ __launch_bounds__(256, 2) void tgemm_nn(int M, int N, int K,
                                                   const float* __restrict__ A,
                                                   const float* __restrict__ B,
                                                   const float* __restrict__ bias,
                                                   const float* __restrict__ res,
                                                   float* __restrict__ C,
                                                   int do_gelu) {
    __shared__ __align__(16) float As[128 * 36];
    __shared__ __align__(16) float Bs[32 * 136];
    const int t = threadIdx.x;
    const int m0 = blockIdx.y * 128;
    const int n0 = blockIdx.x * 128;
    const int warp = t >> 5, lane = t & 31;
    const int quad = lane >> 2, qt = lane & 3;
    const int wm = (warp & 1) * 64;
    const int wn = (warp >> 1) * 32;

    float acc[4][4][4];
#pragma unroll
    for (int i = 0; i < 4; i++)
#pragma unroll
        for (int j = 0; j < 4; j++)
#pragma unroll
            for (int c = 0; c < 4; c++) acc[i][j][c] = 0.f;

    for (int k0 = 0; k0 < K; k0 += 32) {
        // stage A: 128x32
#pragma unroll
        for (int i = 0; i < 4; i++) {
            int f = t + i * 256;
            int row = f >> 3, c4 = (f & 7) * 4;
            float4 v = *reinterpret_cast<const float4*>(&A[(size_t)(m0 + row) * K + k0 + c4]);
            v.x = tf32r(v.x); v.y = tf32r(v.y); v.z = tf32r(v.z); v.w = tf32r(v.w);
            *reinterpret_cast<float4*>(&As[row * 36 + c4]) = v;
        }
        // stage B: 32x128
#pragma unroll
        for (int i = 0; i < 4; i++) {
            int f = t + i * 256;
            int kk = f >> 5, n4 = (f & 31) * 4;
            float4 v = *reinterpret_cast<const float4*>(&B[(size_t)(k0 + kk) * N + n0 + n4]);
            v.x = tf32r(v.x); v.y = tf32r(v.y); v.z = tf32r(v.z); v.w = tf32r(v.w);
            *reinterpret_cast<float4*>(&Bs[kk * 136 + n4]) = v;
        }
        __syncthreads();

#pragma unroll
        for (int ks = 0; ks < 4; ks++) {
            const int kb = ks * 8;
            uint32_t af[4][4];
#pragma unroll
            for (int mi = 0; mi < 4; mi++) {
                int mr = wm + mi * 16 + quad;
                af[mi][0] = __float_as_uint(As[mr * 36 + kb + qt]);
                af[mi][1] = __float_as_uint(As[(mr + 8) * 36 + kb + qt]);
                af[mi][2] = __float_as_uint(As[mr * 36 + kb + qt + 4]);
                af[mi][3] = __float_as_uint(As[(mr + 8) * 36 + kb + qt + 4]);
            }
            uint32_t bf[4][2];
#pragma unroll
            for (int nj = 0; nj < 4; nj++) {
                int nc = wn + nj * 8 + quad;
                bf[nj][0] = __float_as_uint(Bs[(kb + qt) * 136 + nc]);
                bf[nj][1] = __float_as_uint(Bs[(kb + qt + 4) * 136 + nc]);
            }
#pragma unroll
            for (int mi = 0; mi < 4; mi++)
#pragma unroll
                for (int nj = 0; nj < 4; nj++)
                    mma_tf32(acc[mi][nj], af[mi], bf[nj]);
        }
        __syncthreads();
    }

    // epilogue (all Ns here are multiples of 128 -> float2 stores aligned)
#pragma unroll
    for (int mi = 0; mi < 4; mi++) {
#pragma unroll
        for (int nj = 0; nj < 4; nj++) {
            int row0 = m0 + wm + mi * 16 + quad;
            int col0 = n0 + wn + nj * 8 + 2 * qt;
#pragma unroll
            for (int h = 0; h < 2; h++) {
                int r = row0 + h * 8;
                float v0 = acc[mi][nj][h * 2 + 0];
                float v1 = acc[mi][nj][h * 2 + 1];
                if (bias) { v0 += bias[col0]; v1 += bias[col0 + 1]; }
                if (res) {
                    v0 += res[(size_t)r * N + col0];
                    v1 += res[(size_t)r * N + col0 + 1];
                }
                if (do_gelu) { v0 = gelu_f(v0); v1 = gelu_f(v1); }
                *reinterpret_cast<float2*>(&C[(size_t)r * N + col0]) = make_float2(v0, v1);
            }
        }
    }
}

// ================= tf32 tensor-core GEMM (NT) ==================================
// C[M,N] = A[M,K] @ B^T, B is [N,K] row-major (tied lm_head). N=50257 (odd!):
// scalar stores only — row byte offsets are 4 mod 8 for odd rows.
__global__ __launch_bounds__(256, 2) void tgemm_nt(int M, int N, int K,
                                                   const float* __restrict__ A,
                                                   const float* __restrict__ B,
                                                   float* __restrict__ C) {
    __shared__ __align__(16) float As[128 * 36];
    __shared__ __align__(16) float Bs[128 * 36];   // [n][k]
    const int t = threadIdx.x;
    const int m0 = blockIdx.y * 128;
    const int n0 = blockIdx.x * 128;
    const int warp = t >> 5, lane = t & 31;
    const int quad = lane >> 2, qt = lane & 3;
    const int wm = (warp & 1) * 64;
    const int wn = (warp >> 1) * 32;

    float acc[4][4][4];
#pragma unroll
    for (int i = 0; i < 4; i++)
#pragma unroll
        for (int j = 0; j < 4; j++)
#pragma unroll
            for (int c = 0; c < 4; c++) acc[i][j][c] = 0.f;

    for (int k0 = 0; k0 < K; k0 += 32) {
#pragma unroll
        for (int i = 0; i < 4; i++) {
            int f = t + i * 256;
            int row = f >> 3, c4 = (f & 7) * 4;
            float4 v = *reinterpret_cast<const float4*>(&A[(size_t)(m0 + row) * K + k0 + c4]);
            v.x = tf32r(v.x); v.y = tf32r(v.y); v.z = tf32r(v.z); v.w = tf32r(v.w);
            *reinterpret_cast<float4*>(&As[row * 36 + c4]) = v;
        }
#pragma unroll
        for (int i = 0; i < 4; i++) {
            int f = t + i * 256;
            int n = f >> 3, c4 = (f & 7) * 4;
            float4 v = make_float4(0.f, 0.f, 0.f, 0.f);
            if (n0 + n < N)
                v = *reinterpret_cast<const float4*>(&B[(size_t)(n0 + n) * K + k0 + c4]);
            v.x = tf32r(v.x); v.y = tf32r(v.y); v.z = tf32r(v.z); v.w = tf32r(v.w);
            *reinterpret_cast<float4*>(&Bs[n * 36 + c4]) = v;
        }
        __syncthreads();

#pragma unroll
        for (int ks = 0; ks < 4; ks++) {
            const int kb = ks * 8;
            uint32_t af[4][4];
#pragma unroll
            for (int mi = 0; mi < 4; mi++) {
                int mr = wm + mi * 16 + quad;
                af[mi][0] = __float_as_uint(As[mr * 36 + kb + qt]);
                af[mi][1] = __float_as_uint(As[(mr + 8) * 36 + kb + qt]);
                af[mi][2] = __float_as_uint(As[mr * 36 + kb + qt + 4]);
                af[mi][3] = __float_as_uint(As[(mr + 8) * 36 + kb + qt + 4]);
            }
            uint32_t bf[4][2];
#pragma unroll
            for (int nj = 0; nj < 4; nj++) {
                int nc = wn + nj * 8 + quad;
                bf[nj][0] = __float_as_uint(Bs[nc * 36 + kb + qt]);
                bf[nj][1] = __float_as_uint(Bs[nc * 36 + kb + qt + 4]);
            }
#pragma unroll
            for (int mi = 0; mi < 4; mi++)
#pragma unroll
                for (int nj = 0; nj < 4; nj++)
                    mma_tf32(acc[mi][nj], af[mi], bf[nj]);
        }
        __syncthreads();
    }

#pragma unroll
    for (int mi = 0; mi < 4; mi++) {
#pragma unroll
        for (int nj = 0; nj < 4; nj++) {
            int row0 = m0 + wm + mi * 16 + quad;
            int col0 = n0 + wn + nj * 8 + 2 * qt;
#pragma unroll
            for (int h = 0; h < 2; h++) {
                int r = row0 + h * 8;
                // scalar stores: N is odd, float2 would misalign on odd rows
                if (col0 < N)     C[(size_t)r * N + col0]     = acc[mi][nj][h * 2 + 0];
                if (col0 + 1 < N) C[(size_t)r * N + col0 + 1] = acc[mi][nj][h * 2 + 1];
            }
        }
    }
}

// ---------------- fused causal attention (per query row) -----------------------
__global__ __launch_bounds__(128) void attn_kernel(const float* __restrict__ qkv,
                                                   float* __restrict__ out) {
    __shared__ float sq[HDIM];
    __shared__ float ss[TSEQ];
    __shared__ float red[4];
    int tq = blockIdx.x;
    int h = blockIdx.y;
    int b = blockIdx.z;
    int tid = threadIdx.x;

    const int row = b * TSEQ + tq;
    const float* qptr = qkv + (size_t)row * (3 * EDIM) + h * HDIM;
    if (tid < HDIM) sq[tid] = qptr[tid];
    __syncthreads();

    const int nk = tq + 1;
    const float* kbase = qkv + (size_t)b * TSEQ * (3 * EDIM) + EDIM + h * HDIM;
    const float* vbase = qkv + (size_t)b * TSEQ * (3 * EDIM) + 2 * EDIM + h * HDIM;
    const float4* sq4 = reinterpret_cast<const float4*>(sq);

    float lmax = -1e30f;
    for (int k = tid; k < nk; k += 128) {
        const float4* kp4 = reinterpret_cast<const float4*>(kbase + (size_t)k * (3 * EDIM));
        float dot = 0.f;
#pragma unroll
        for (int d = 0; d < 16; d++) {
            float4 kv = kp4[d];
            float4 qv = sq4[d];
            dot = fmaf(qv.x, kv.x, dot);
            dot = fmaf(qv.y, kv.y, dot);
            dot = fmaf(qv.z, kv.z, dot);
            dot = fmaf(qv.w, kv.w, dot);
        }
        dot *= 0.125f;
        ss[k] = dot;
        lmax = fmaxf(lmax, dot);
    }
    float gmax = block_max(lmax, red, 4);

    float lsum = 0.f;
    for (int k = tid; k < nk; k += 128) {
        float e = __expf(ss[k] - gmax);
        ss[k] = e;
        lsum += e;
    }
    float gsum = block_sum(lsum, red, 4);
    float inv = 1.0f / gsum;
    __syncthreads();

    if (tid < HDIM) {
        float a0 = 0.f, a1 = 0.f, a2 = 0.f, a3 = 0.f;
        int k = 0;
        for (; k + 4 <= nk; k += 4) {
            a0 = fmaf(ss[k + 0], vbase[(size_t)(k + 0) * (3 * EDIM) + tid], a0);
            a1 = fmaf(ss[k + 1], vbase[(size_t)(k + 1) * (3 * EDIM) + tid], a1);
            a2 = fmaf(ss[k + 2], vbase[(size_t)(k + 2) * (3 * EDIM) + tid], a2);
            a3 = fmaf(ss[k + 3], vbase[(size_t)(k + 3) * (3 * EDIM) + tid], a3);
        }
        for (; k < nk; k++)
            a0 = fmaf(ss[k], vbase[(size_t)k * (3 * EDIM) + tid], a0);
        out[(size_t)row * EDIM + h * HDIM + tid] = (a0 + a1 + a2 + a3) * inv;
    }
}

// ---------------- launch -------------------------------------------------------
extern "C" void kernel_launch(void* const* d_in, const int* in_sizes, int n_in,
                              void* d_out, int out_size) {
    const int* idx = (const int*)d_in[0];
    const float* wte = (const float*)d_in[1];
    const float* wpe = (const float*)d_in[2];
    const float* ln1_w = (const float*)d_in[3];
    const float* ln1_b = (const float*)d_in[4];
    const float* attn_w = (const float*)d_in[5];
    const float* attn_b = (const float*)d_in[6];
    const float* attn_proj_w = (const float*)d_in[7];
    const float* attn_proj_b = (const float*)d_in[8];
    const float* ln2_w = (const float*)d_in[9];
    const float* ln2_b = (const float*)d_in[10];
    const float* fc_w = (const float*)d_in[11];
    const float* fc_b = (const float*)d_in[12];
    const float* fc_proj_w = (const float*)d_in[13];
    const float* fc_proj_b = (const float*)d_in[14];
    const float* lnf_w = (const float*)d_in[15];
    const float* lnf_b = (const float*)d_in[16];
    float* out = (float*)d_out;

    float *x, *ln, *qkv, *attn, *fc;
    cudaGetSymbolAddress((void**)&x, g_x);
    cudaGetSymbolAddress((void**)&ln, g_ln);
    cudaGetSymbolAddress((void**)&qkv, g_qkv);
    cudaGetSymbolAddress((void**)&attn, g_attn);
    cudaGetSymbolAddress((void**)&fc, g_fc);

    embed_kernel<<<MROWS, 256>>>(idx, wte, wpe, x);

    for (int l = 0; l < LNUM; l++) {
        ln_kernel<<<MROWS, 256>>>(x, ln1_w + l * EDIM, ln1_b + l * EDIM, ln);
        tgemm_nn<<<dim3(3 * EDIM / 128, MROWS / 128), 256>>>(
            MROWS, 3 * EDIM, EDIM, ln, attn_w + (size_t)l * EDIM * 3 * EDIM,
            attn_b + (size_t)l * 3 * EDIM, nullptr, qkv, 0);
        attn_kernel<<<dim3(TSEQ, HNUM, BATCH), 128>>>(qkv, attn);
        tgemm_nn<<<dim3(EDIM / 128, MROWS / 128), 256>>>(
            MROWS, EDIM, EDIM, attn, attn_proj_w + (size_t)l * EDIM * EDIM,
            attn_proj_b + (size_t)l * EDIM, x, x, 0);
        ln_kernel<<<MROWS, 256>>>(x, ln2_w + l * EDIM, ln2_b + l * EDIM, ln);
        tgemm_nn<<<dim3(4 * EDIM / 128, MROWS / 128), 256>>>(
            MROWS, 4 * EDIM, EDIM, ln, fc_w + (size_t)l * EDIM * 4 * EDIM,
            fc_b + (size_t)l * 4 * EDIM, nullptr, fc, 1);
        tgemm_nn<<<dim3(EDIM / 128, MROWS / 128), 256>>>(
            MROWS, EDIM, 4 * EDIM, fc, fc_proj_w + (size_t)l * 4 * EDIM * EDIM,
            fc_proj_b + (size_t)l * EDIM, x, x, 0);
    }

    ln_kernel<<<MROWS, 256>>>(x, lnf_w, lnf_b, ln);
    tgemm_nt<<<dim3((VOCAB + 127) / 128, MROWS / 128), 256>>>(
        MROWS, VOCAB, EDIM, ln, wte, out);
}